// round 16
// baseline (speedup 1.0000x reference)
#include <cuda_runtime.h>
#include <cuda_bf16.h>

#define T_N 1024
#define C_N 768
#define H_N 12
#define D_N 64
#define NT_N 8
#define LOG2E 1.4426950408889634f

// ---------------- scratch (static device globals; no allocation) ----------------
__device__ float g_q[H_N * T_N * D_N];       // [H][T][D]
__device__ float g_k[H_N * T_N * D_N];
__device__ float g_v[H_N * T_N * D_N];
__device__ float g_g[H_N * T_N * D_N];       // rmsnormed+tf32-quantized g (written by gemm epilogue)
__device__ float g_g2[H_N * T_N];            // ||ghat||^2 per (h,t)
__device__ float g_y[T_N * C_N];             // attention out, [T][C] layout
__device__ unsigned g_red[H_N][3];           // per-head max ||q||^2, ||k||^2, g2 (uint-ordered)
__device__ float g_op[3 * T_N * C_N];        // split-k partials for out projection
__device__ unsigned g_cnt[96];               // split-k tile counters (6 x 16)

// split-j partials: 40 units per head (chunks of <=4 j-tiles), all at scale 2^-M
__device__ float g_pacc[H_N * 40 * 64 * 64]; // [h][unit][row][col]
__device__ float g_pl[H_N * 40 * 64];
__device__ float g_dw[H_N * 16 * 64];        // diag weights per (h,it,row)

// unit tables: heavy (4-tile) units first for scheduling
__constant__ int c_uit[40] = {15,15,15,15,14,14,14,13,13,13,12,12,12,11,11,11,10,10,9,9,8,8,7,7,6,5,4,3,
                              14,10,6,2, 13,9,5,1, 12,8,4,0};
__constant__ int c_uc[40]  = { 0, 1, 2, 3, 0, 1, 2, 0, 1, 2, 0, 1, 2, 0, 1, 2, 0, 1,0,1,0,1,0,1,0,0,0,0,
                               3, 2,1,0,  3,2,1,0,  3,2,1,0};
__constant__ int c_off[16] = {0,1,2,3,4,6,8,10,12,15,18,21,24,28,32,36};

struct Consts {
    float inv4tau[H_N][NT_N];
    float wte[H_N][NT_N];
    float neghb[H_N];
    float dpl[H_N];           // lam * dp_scale/(8*0.8)
    float glk[H_N];           // (1-lam) * logk_scale * ln2
    float outs[H_N];
    float fA[H_N], fB[H_N], i4t0[H_N];
    int   fastf[H_N];
    float alpha;
};
__device__ Consts g_c;

__device__ __forceinline__ float ex2f_(float x){ float y; asm("ex2.approx.ftz.f32 %0, %1;":"=f"(y):"f"(x)); return y; }
__device__ __forceinline__ float lg2f_(float x){ float y; asm("lg2.approx.ftz.f32 %0, %1;":"=f"(y):"f"(x)); return y; }
__device__ __forceinline__ unsigned f2tf32(float x){ unsigned y; asm("cvt.rna.tf32.f32 %0, %1;":"=r"(y):"f"(x)); return y; }

__device__ __forceinline__ void mma_tf32(float* d, const unsigned* a, const unsigned* b) {
    asm volatile(
      "mma.sync.aligned.m16n8k8.row.col.f32.tf32.tf32.f32 "
      "{%0,%1,%2,%3}, {%4,%5,%6,%7}, {%8,%9}, {%0,%1,%2,%3};\n"
      : "+f"(d[0]), "+f"(d[1]), "+f"(d[2]), "+f"(d[3])
      : "r"(a[0]), "r"(a[1]), "r"(a[2]), "r"(a[3]), "r"(b[0]), "r"(b[1]));
}

// ---------------- constants precompute (parallel over heads; zero reduce cells + split-k counters) ----------------
__global__ void const_kernel(const float* lam_p, const float* log_tau,
                             const float* logit_w, const float* beta,
                             const float* out_scale, const float* dp_scale,
                             const float* logk_scale, const float* dt_logit) {
    if (blockIdx.x != 0) return;
    for (int i = threadIdx.x; i < 96; i += 32) g_cnt[i] = 0u;
    int h = threadIdx.x;
    if (h >= H_N) return;
    float lam = lam_p[0];
    g_red[h][0] = 0u; g_red[h][1] = 0u; g_red[h][2] = 0u;
    float mx = -1e30f;
    for (int t = 0; t < NT_N; ++t) mx = fmaxf(mx, logit_w[h*NT_N+t]);
    float s = 0.f, e[NT_N];
    for (int t = 0; t < NT_N; ++t) { e[t] = expf(logit_w[h*NT_N+t]-mx); s += e[t]; }
    float W = 0.f;
    for (int t = 0; t < NT_N; ++t) { g_c.wte[h][t] = e[t]/s + 1e-12f; W += g_c.wte[h][t]; }
    for (int t = 0; t < NT_N; ++t) {
        float tau = fmaxf(expf(log_tau[h*NT_N+t]), 1e-6f);
        g_c.inv4tau[h][t] = 1.f/(4.f*tau);
    }
    float bc = fminf(fmaxf(beta[h], 0.5f), 2.5f);
    float neghb = -0.5f*bc;
    float dpc = dp_scale[h]/(8.0f*0.8f);
    float lks = logk_scale[h]*0.6931471805599453f;
    g_c.neghb[h] = neghb;
    g_c.dpl[h]   = lam*dpc;
    g_c.glk[h]   = (1.f-lam)*lks;
    g_c.outs[h]  = out_scale[h];
    int same = 1;
    for (int t = 1; t < NT_N; ++t) if (g_c.inv4tau[h][t] != g_c.inv4tau[h][0]) same = 0;
    g_c.fastf[h] = same;
    g_c.i4t0[h]  = g_c.inv4tau[h][0];
    g_c.fA[h]    = g_c.glk[h]*neghb;
    g_c.fB[h]    = g_c.glk[h]*log2f(W);
    if (h == 0) g_c.alpha = 0.1f/(1.f+expf(-dt_logit[0]));
}

// ---------------- tf32 GEMM 64x128, double-buffered, k-range ----------------
// scatter=1: qkvg path with fused head-scatter + rmsnorm(g) + norm maxes
// outp!=nullptr: fused split-k serial reduction (last z-CTA per tile sums partials)
#define GS 36
#define STG64 ((64+128)*GS)

__global__ __launch_bounds__(256, 3) void gemm_tf32_64(const float* __restrict__ A,
        const float* __restrict__ B, float* __restrict__ C, int M, int N, int Kst,
        int klen, int scatter, const float* __restrict__ gnw, float* __restrict__ outp) {
    extern __shared__ unsigned gsm[];
    int tid = threadIdx.x;
    int lane = tid & 31, w = tid >> 5;
    int wm = w >> 2, wn = w & 3;
    int m0 = blockIdx.y*64, n0 = blockIdx.x*128;
    int k0 = blockIdx.z*klen;
    int lr = tid >> 3, lc = (tid & 7)*4;
    const float* Ap = A + (size_t)(m0+lr)*Kst + k0 + lc;
    const float* Bp = B + (size_t)(n0+lr)*Kst + k0 + lc;

    float acc[2][4][4];
    #pragma unroll
    for (int i = 0; i < 2; ++i)
        #pragma unroll
        for (int j = 0; j < 4; ++j)
            #pragma unroll
            for (int v = 0; v < 4; ++v) acc[i][j][v] = 0.f;

    int qa = lane >> 2, ra = lane & 3;

    float4 pra[2], prb[4];
    #pragma unroll
    for (int p = 0; p < 2; ++p) pra[p] = *(const float4*)(Ap + (size_t)p*32*Kst);
    #pragma unroll
    for (int p = 0; p < 4; ++p) prb[p] = *(const float4*)(Bp + (size_t)p*32*Kst);
    {
        unsigned* As = gsm;
        unsigned* Bs = gsm + 64*GS;
        #pragma unroll
        for (int p = 0; p < 2; ++p) {
            unsigned* as = As + (lr + p*32)*GS + lc;
            as[0]=f2tf32(pra[p].x); as[1]=f2tf32(pra[p].y); as[2]=f2tf32(pra[p].z); as[3]=f2tf32(pra[p].w);
        }
        #pragma unroll
        for (int p = 0; p < 4; ++p) {
            unsigned* bs = Bs + (lr + p*32)*GS + lc;
            bs[0]=f2tf32(prb[p].x); bs[1]=f2tf32(prb[p].y); bs[2]=f2tf32(prb[p].z); bs[3]=f2tf32(prb[p].w);
        }
    }
    __syncthreads();
    int cur = 0;

    for (int kb = 0; kb < klen; kb += 32) {
        bool nxt = (kb + 32 < klen);
        if (nxt) {
            #pragma unroll
            for (int p = 0; p < 2; ++p) pra[p] = *(const float4*)(Ap + (size_t)p*32*Kst + kb + 32);
            #pragma unroll
            for (int p = 0; p < 4; ++p) prb[p] = *(const float4*)(Bp + (size_t)p*32*Kst + kb + 32);
        }
        unsigned* As = gsm + cur*STG64;
        unsigned* Bs = As + 64*GS;
        #pragma unroll
        for (int ks = 0; ks < 4; ++ks) {
            unsigned af[2][4], bf[4][2];
            #pragma unroll
            for (int mt = 0; mt < 2; ++mt) {
                const unsigned* p = As + (wm*32 + mt*16 + qa)*GS + ks*8 + ra;
                af[mt][0] = p[0];
                af[mt][1] = p[8*GS];
                af[mt][2] = p[4];
                af[mt][3] = p[8*GS + 4];
            }
            #pragma unroll
            for (int nt = 0; nt < 4; ++nt) {
                const unsigned* p = Bs + (wn*32 + nt*8 + qa)*GS + ks*8 + ra;
                bf[nt][0] = p[0];
                bf[nt][1] = p[4];
            }
            #pragma unroll
            for (int mt = 0; mt < 2; ++mt)
                #pragma unroll
                for (int nt = 0; nt < 4; ++nt)
                    mma_tf32(acc[mt][nt], af[mt], bf[nt]);
        }
        if (nxt) {
            unsigned* As2 = gsm + (cur^1)*STG64;
            unsigned* Bs2 = As2 + 64*GS;
            #pragma unroll
            for (int p = 0; p < 2; ++p) {
                unsigned* as = As2 + (lr + p*32)*GS + lc;
                as[0]=f2tf32(pra[p].x); as[1]=f2tf32(pra[p].y); as[2]=f2tf32(pra[p].z); as[3]=f2tf32(pra[p].w);
            }
            #pragma unroll
            for (int p = 0; p < 4; ++p) {
                unsigned* bs = Bs2 + (lr + p*32)*GS + lc;
                bs[0]=f2tf32(prb[p].x); bs[1]=f2tf32(prb[p].y); bs[2]=f2tf32(prb[p].z); bs[3]=f2tf32(prb[p].w);
            }
            __syncthreads();
            cur ^= 1;
        }
    }

    if (!scatter) {
        float* Cp = C + (size_t)blockIdx.z*M*N;
        #pragma unroll
        for (int mt = 0; mt < 2; ++mt) {
            int row = m0 + wm*32 + mt*16 + qa;
            #pragma unroll
            for (int nt = 0; nt < 4; ++nt) {
                int col = n0 + wn*32 + nt*8 + ra*2;
                float2 c0 = {acc[mt][nt][0], acc[mt][nt][1]};
                float2 c1 = {acc[mt][nt][2], acc[mt][nt][3]};
                *(float2*)(Cp + (size_t)row*N + col) = c0;
                *(float2*)(Cp + (size_t)(row+8)*N + col) = c1;
            }
        }
        if (outp) {
            // fused split-k serial reduction: last z-CTA of this (x,y) tile sums p0+p1+p2
            __threadfence();
            __syncthreads();           // all partial stores issued before the arrive
            if (tid == 0) gsm[0] = atomicAdd(&g_cnt[blockIdx.y*6 + blockIdx.x], 1u);
            __syncthreads();
            if (gsm[0] == 2u) {
                __threadfence();       // order reads after observing both arrivals
                const float* p0 = C;
                const float* p1 = C + (size_t)M*N;
                const float* p2 = C + (size_t)2*M*N;
                #pragma unroll
                for (int p = 0; p < 8; ++p) {
                    int f = tid + p*256;
                    int row = m0 + (f >> 5), c4 = n0 + (f & 31)*4;
                    size_t gidx = (size_t)row*N + c4;
                    float4 a = *(const float4*)(p0 + gidx);
                    float4 b = *(const float4*)(p1 + gidx);
                    float4 c = *(const float4*)(p2 + gidx);
                    float4 o;
                    o.x = a.x + b.x + c.x;
                    o.y = a.y + b.y + c.y;
                    o.z = a.z + b.z + c.z;
                    o.w = a.w + b.w + c.w;
                    *(float4*)(outp + gidx) = o;
                }
            }
        }
        return;
    }

    // ---- scatter path: stage tile, fused rmsnorm(g)/norm maxes ----
    __syncthreads();   // stage buffers free
    float* epi = (float*)gsm;       // [64][132]
    #pragma unroll
    for (int mt = 0; mt < 2; ++mt) {
        int row = wm*32 + mt*16 + qa;
        #pragma unroll
        for (int nt = 0; nt < 4; ++nt) {
            int col = wn*32 + nt*8 + ra*2;
            float2 c0 = {acc[mt][nt][0], acc[mt][nt][1]};
            float2 c1 = {acc[mt][nt][2], acc[mt][nt][3]};
            *(float2*)(epi + row*132 + col) = c0;
            *(float2*)(epi + (row+8)*132 + col) = c1;
        }
    }
    __syncthreads();
    int sec = n0 / C_N;            // 0:q 1:k 2:v 3:g (uniform per CTA)
    int hh0 = (n0 % C_N) >> 6;     // first of two heads in this tile
    float* psm = epi + 64*132;     // 128 ss cells (tail of smem)

    if (sec != 2) {
        int pr = tid >> 1, hf = tid & 1;
        int row = pr >> 1, hd = pr & 1;
        const float* rp = epi + row*132 + hd*64 + hf*32;
        float ss = 0.f;
        #pragma unroll
        for (int c = 0; c < 32; c += 4) {
            float4 v = *(const float4*)(rp + c);
            ss += v.x*v.x + v.y*v.y + v.z*v.z + v.w*v.w;
        }
        ss += __shfl_xor_sync(0xffffffffu, ss, 1);
        if (sec == 3) {
            float r = rsqrtf(ss*(1.0f/D_N) + 1e-6f);
            float s2h = 0.f;
            int grow = (hh0 + hd)*T_N + m0 + row;
            #pragma unroll
            for (int c = 0; c < 32; c += 4) {
                int dd = hf*32 + c;
                float4 v = *(const float4*)(rp + c);
                float4 wv = *(const float4*)(gnw + dd);
                float4 qv;
                qv.x = __uint_as_float(f2tf32(v.x*r*wv.x));
                qv.y = __uint_as_float(f2tf32(v.y*r*wv.y));
                qv.z = __uint_as_float(f2tf32(v.z*r*wv.z));
                qv.w = __uint_as_float(f2tf32(v.w*r*wv.w));
                s2h += qv.x*qv.x + qv.y*qv.y + qv.z*qv.z + qv.w*qv.w;
                *(float4*)(g_g + (size_t)grow*D_N + dd) = qv;
            }
            s2h += __shfl_xor_sync(0xffffffffu, s2h, 1);
            if (hf == 0) { g_g2[grow] = s2h; psm[pr] = s2h; }
        } else {
            if (hf == 0) psm[pr] = ss;
        }
    }
    if (sec != 3) {
        float* base = (sec == 0) ? g_q : (sec == 1) ? g_k : g_v;
        #pragma unroll
        for (int p = 0; p < 8; ++p) {
            int f = tid + p*256;
            int row = f >> 5, c4 = (f & 31)*4;
            float4 v = *(const float4*)(epi + row*132 + c4);
            int hd = c4 >> 6, dd = c4 & 63;
            *(float4*)(base + ((size_t)((hh0+hd)*T_N + m0 + row))*D_N + dd) = v;
        }
    }
    __syncthreads();
    if (tid < 2 && sec != 2) {
        float mx = 0.f;
        #pragma unroll 4
        for (int rr = 0; rr < 64; ++rr) mx = fmaxf(mx, psm[rr*2 + tid]);
        int cell = (sec == 3) ? 2 : sec;
        atomicMax(&g_red[hh0 + tid][cell], __float_as_uint(mx));
    }
}

// ---------------- split-j flash attention partial (fixed-max, paired LDS.64 frags) ----------------
#define QG_O   0                // uint2[64][68]: (q tf32, g tf32)
#define KG_O   8704             // uint2[64][68]: (k tf32, g tf32)
#define VS_O   17408            // 72 rows x 68 (row 64 = ones for row-sum, 65-71 zero)
#define PS_O   22304
#define G2I_O  26656
#define G2J_O  26720
#define DWS_O  26784
#define ATT_SMEM_WORDS 26848
#define ATT_SMEM_BYTES (ATT_SMEM_WORDS*4)

__global__ __launch_bounds__(256, 2) void attn_part() {
    extern __shared__ unsigned smu[];
    float* smf = (float*)smu;
    unsigned* Vs  = smu + VS_O;
    unsigned* Ps  = smu + PS_O;
    float* g2i_s = smf + G2I_O;
    float* g2j_s = smf + G2J_O;
    float* dws   = smf + DWS_O;

    int bid = blockIdx.x;
    int h = bid % H_N;
    int u = bid / H_N;
    int it = c_uit[u], cch = c_uc[u];
    int i0 = it * 64;
    int jt0 = cch*4, jt1 = min(jt0+3, it);
    int uidx = c_off[it] + cch;
    int tid = threadIdx.x;
    int lane = tid & 31, w = tid >> 5;
    int wm = w >> 1, wn = w & 1;
    int qa = lane >> 2, ra = lane & 3;
    int row0 = wm*16 + qa;

    int fast = g_c.fastf[h];
    float i4t0 = g_c.i4t0[h];
    float neghb = g_c.neghb[h];

    // ---- derive safe max M from reduced norms ----
    float M2;
    {
        float mq = __uint_as_float(g_red[h][0]);
        float mk = __uint_as_float(g_red[h][1]);
        float mg = __uint_as_float(g_red[h][2]);
        float dplL_ = g_c.dpl[h]*LOG2E;
        float bqk = fabsf(dplL_)*sqrtf(mq*mk);
        float smax = 4.f*mg + 1.f;
        float kmax;
        if (fast) {
            float a = g_c.fA[h]*LOG2E, b = g_c.fB[h]*LOG2E;
            float t1 = fmaf(a, log2f(fmaf(smax, i4t0, 1.f)), b);
            kmax = fmaxf(t1, b);
        } else {
            float glkL_ = g_c.glk[h]*LOG2E;
            float W = 0.f, Kmin = 0.f;
            #pragma unroll
            for (int t = 0; t < NT_N; ++t) {
                W += g_c.wte[h][t];
                Kmin += g_c.wte[h][t]*powf(fmaf(smax, g_c.inv4tau[h][t], 1.f), neghb);
            }
            kmax = fmaxf(glkL_*log2f(W), glkL_*log2f(Kmin));
        }
        M2 = bqk + kmax + 1.f;
    }
    float dplL = g_c.dpl[h]*LOG2E;
    float fAL  = g_c.fA[h]*LOG2E;
    float fBM  = g_c.fB[h]*LOG2E - M2;
    float glkL = g_c.glk[h]*LOG2E;
    float mneg = -M2;

    const float* qg  = g_q + (size_t)(h*T_N + i0)*D_N;
    const float* gig = g_g + (size_t)(h*T_N + i0)*D_N;
    #pragma unroll
    for (int p = 0; p < 4; ++p) {
        int e = tid + p*256;
        int r = e >> 4, dc = (e & 15)*4;
        float4 a = *(const float4*)(qg + r*D_N + dc);
        float4 b = *(const float4*)(gig + r*D_N + dc);   // already tf32-quantized
        uint4 w0, w1;
        w0.x = f2tf32(a.x); w0.y = __float_as_uint(b.x);
        w0.z = f2tf32(a.y); w0.w = __float_as_uint(b.y);
        w1.x = f2tf32(a.z); w1.y = __float_as_uint(b.z);
        w1.z = f2tf32(a.w); w1.w = __float_as_uint(b.w);
        *(uint4*)(smu + QG_O + (r*68 + dc)*2) = w0;
        *(uint4*)(smu + QG_O + (r*68 + dc)*2 + 4) = w1;
    }
    if (tid < 64) g2i_s[tid] = g_g2[h*T_N + i0 + tid];
    // ones row (64) + zero rows (65-71) of Vs — written once, never overwritten
    for (int z = tid; z < 8*68; z += 256)
        Vs[64*68 + z] = (z < 64) ? f2tf32(1.f) : 0u;

    float apv[5][4];
    #pragma unroll
    for (int nt = 0; nt < 5; ++nt)
        #pragma unroll
        for (int c = 0; c < 4; ++c) apv[nt][c] = 0.f;

    for (int jt = jt0; jt <= jt1; ++jt) {
        int j0 = jt*64;
        __syncthreads();   // prev tile's Ps/Vs reads done
        const float* kg  = g_k + (size_t)(h*T_N + j0)*D_N;
        const float* gjg = g_g + (size_t)(h*T_N + j0)*D_N;
        const float* vg  = g_v + (size_t)(h*T_N + j0)*D_N;
        #pragma unroll
        for (int p = 0; p < 4; ++p) {
            int e = tid + p*256;
            int r = e >> 4, dc = (e & 15)*4;
            float4 a = *(const float4*)(kg + r*D_N + dc);
            float4 b = *(const float4*)(gjg + r*D_N + dc);
            uint4 w0, w1;
            w0.x = f2tf32(a.x); w0.y = __float_as_uint(b.x);
            w0.z = f2tf32(a.y); w0.w = __float_as_uint(b.y);
            w1.x = f2tf32(a.z); w1.y = __float_as_uint(b.z);
            w1.z = f2tf32(a.w); w1.w = __float_as_uint(b.w);
            *(uint4*)(smu + KG_O + (r*68 + dc)*2) = w0;
            *(uint4*)(smu + KG_O + (r*68 + dc)*2 + 4) = w1;
            int j = e & 63, dg = (e >> 6)*4;
            float4 v = *(const float4*)(vg + j*D_N + dg);
            Vs[(dg+0)*68 + j] = f2tf32(v.x);
            Vs[(dg+1)*68 + j] = f2tf32(v.y);
            Vs[(dg+2)*68 + j] = f2tf32(v.z);
            Vs[(dg+3)*68 + j] = f2tf32(v.w);
        }
        if (tid < 64) g2j_s[tid] = g_g2[h*T_N + j0 + tid];
        __syncthreads();

        // ---- QK + GG MMAs (paired LDS.64 fragment loads) ----
        float dqk[4][4], dgg[4][4];
        #pragma unroll
        for (int nt = 0; nt < 4; ++nt)
            #pragma unroll
            for (int c = 0; c < 4; ++c) { dqk[nt][c] = 0.f; dgg[nt][c] = 0.f; }

        #pragma unroll
        for (int ks = 0; ks < 8; ++ks) {
            int kc = ks*8 + ra;
            const uint2* qgp = (const uint2*)(smu + QG_O) + row0*68 + kc;
            uint2 w0 = qgp[0], w1 = qgp[8*68], w2 = qgp[4], w3 = qgp[8*68+4];
            unsigned af[4] = {w0.x, w1.x, w2.x, w3.x};
            unsigned gf[4] = {w0.y, w1.y, w2.y, w3.y};
            #pragma unroll
            for (int nt = 0; nt < 4; ++nt) {
                int nb = wn*32 + nt*8 + qa;
                const uint2* kgp = (const uint2*)(smu + KG_O) + nb*68 + kc;
                uint2 u0 = kgp[0], u1 = kgp[4];
                unsigned bf[2] = {u0.x, u1.x};
                unsigned bgf[2] = {u0.y, u1.y};
                mma_tf32(dqk[nt], af, bf);
                mma_tf32(dgg[nt], gf, bgf);
            }
        }

        // ---- epilogue: p = 2^(score - M) ----
        int diag = (jt == it);
        if (!diag && fast) {
            #pragma unroll
            for (int nt = 0; nt < 4; ++nt) {
                #pragma unroll
                for (int c = 0; c < 4; ++c) {
                    int rl = row0 + (c >> 1)*8;
                    int cl = wn*32 + nt*8 + 2*ra + (c & 1);
                    float s = fmaxf(g2i_s[rl] + g2j_s[cl] - 2.f*dgg[nt][c], 0.f);
                    dqk[nt][c] = ex2f_(fmaf(dqk[nt][c], dplL,
                                     fmaf(fAL, lg2f_(fmaf(s, i4t0, 1.f)), fBM)));
                }
            }
        } else {
            #pragma unroll
            for (int nt = 0; nt < 4; ++nt) {
                #pragma unroll
                for (int c = 0; c < 4; ++c) {
                    int rh = c >> 1, pp = c & 1;
                    int rl = row0 + rh*8;
                    int cl = wn*32 + nt*8 + 2*ra + pp;
                    float p = 0.f;
                    if (j0 + cl <= i0 + rl) {
                        float s = fmaxf(g2i_s[rl] + g2j_s[cl] - 2.f*dgg[nt][c], 0.f);
                        float blc;
                        if (fast) {
                            blc = fmaf(dqk[nt][c], dplL, fmaf(fAL, lg2f_(fmaf(s, i4t0, 1.f)), fBM));
                        } else {
                            float Ksum = 0.f;
                            #pragma unroll
                            for (int t = 0; t < 8; ++t) {
                                float uu = fmaf(s, g_c.inv4tau[h][t], 1.f);
                                Ksum = fmaf(g_c.wte[h][t], ex2f_(neghb * lg2f_(uu)), Ksum);
                            }
                            blc = fmaf(dqk[nt][c], dplL, fmaf(glkL, lg2f_(Ksum), mneg));
                        }
                        p = ex2f_(blc);
                    }
                    dqk[nt][c] = p;
                }
                if (diag) {
                    int cl = wn*32 + nt*8 + 2*ra;
                    if (row0 == cl) dws[row0] = dqk[nt][0];
                    else if (row0 == cl+1) dws[row0] = dqk[nt][1];
                    if (row0+8 == cl) dws[row0+8] = dqk[nt][2];
                    else if (row0+8 == cl+1) dws[row0+8] = dqk[nt][3];
                }
            }
        }
        // shared Ps stores (tf32)
        #pragma unroll
        for (int nt = 0; nt < 4; ++nt) {
            int cl = wn*32 + nt*8 + 2*ra;
            uint2 s0; s0.x = f2tf32(dqk[nt][0]); s0.y = f2tf32(dqk[nt][1]);
            uint2 s1; s1.x = f2tf32(dqk[nt][2]); s1.y = f2tf32(dqk[nt][3]);
            *(uint2*)(Ps + row0*68 + cl) = s0;
            *(uint2*)(Ps + (row0+8)*68 + cl) = s1;
        }
        __syncthreads();   // Ps (and dws) visible

        // ---- PV MMAs (k=64; wn==1 adds ones-column for row-sum l) ----
        #pragma unroll
        for (int ks = 0; ks < 8; ++ks) {
            int kc = ks*8 + ra;
            const unsigned* pp_ = Ps + row0*68 + kc;
            unsigned pf[4] = {pp_[0], pp_[8*68], pp_[4], pp_[8*68+4]};
            #pragma unroll
            for (int nt = 0; nt < 5; ++nt) {
                if (nt == 4 && wn == 0) break;
                const unsigned* vp = Vs + (wn*32 + nt*8 + qa)*68 + kc;
                unsigned vf[2] = {vp[0], vp[4]};
                mma_tf32(apv[nt], pf, vf);
            }
        }
    }

    if (it < 4) {
        // ---- single-chunk unit: finalize directly into g_y (skip partials) ----
        float* Ls = g2j_s;   // reuse: 64 row sums
        if (wn == 1 && ra == 0) { Ls[row0] = apv[4][0]; Ls[row0+8] = apv[4][2]; }
        __syncthreads();
        float alpha = g_c.alpha;
        float ca = 1.f - alpha;
        float outs = g_c.outs[h];
        #pragma unroll
        for (int rh = 0; rh < 2; ++rh) {
            int row = row0 + rh*8;
            float linv = 1.f / fmaxf(Ls[row], 1e-33f);
            float pii = dws[row] * linv;
            float cb = alpha / (1.f + pii);
            #pragma unroll
            for (int nt = 0; nt < 4; ++nt) {
                int cl = wn*32 + nt*8 + 2*ra;
                float p0 = apv[nt][2*rh]*linv, p1 = apv[nt][2*rh+1]*linv;
                float2 v = *(const float2*)(g_v + (size_t)(h*T_N + i0 + row)*D_N + cl);
                float2 o;
                o.x = outs * (ca*p0 + cb*(p0 + pii*v.x));
                o.y = outs * (ca*p1 + cb*(p1 + pii*v.y));
                *(float2*)(g_y + (size_t)(i0 + row)*C_N + h*D_N + cl) = o;
            }
        }
        return;
    }

    // ---- write partials (all at common scale 2^-M, no merge needed) ----
    int base = (h*40 + uidx)*64;
    #pragma unroll
    for (int nt = 0; nt < 4; ++nt) {
        int cl = wn*32 + nt*8 + 2*ra;
        float2 a0 = {apv[nt][0], apv[nt][1]};
        float2 a1 = {apv[nt][2], apv[nt][3]};
        *(float2*)(g_pacc + (size_t)(base + row0)*64 + cl) = a0;
        *(float2*)(g_pacc + (size_t)(base + row0 + 8)*64 + cl) = a1;
    }
    if (wn == 1 && ra == 0) {
        g_pl[base + row0]     = apv[4][0];
        g_pl[base + row0 + 8] = apv[4][2];
    }
    if (jt1 == it && tid < 64) g_dw[(h*16 + it)*64 + tid] = dws[tid];
}

// ---------------- combine partials -> g_y (it>=4 only; quarter-split grid) ----------------
__global__ __launch_bounds__(256) void attn_combine() {
    int bid = blockIdx.x;                 // 576 = 12 heads x 12 itiles(4..15) x 4 quarters
    int h = bid % H_N;
    int rest = bid / H_N;                 // 0..47
    int it = 4 + (rest >> 2), quarter = rest & 3;
    int i0 = it * 64;
    int nc = it/4 + 1;
    int tid = threadIdx.x;
    int row = tid >> 2;
    int c0 = (tid & 3)*4 + quarter*16;
    int b0 = (h*40 + c_off[it])*64 + row;

    float L = 0.f;
    for (int c = 0; c < nc; ++c) L += g_pl[b0 + c*64];
    float linv = 1.f / fmaxf(L, 1e-33f);
    float pii = g_dw[(h*16 + it)*64 + row] * linv;
    float alpha = g_c.alpha;
    float ca = 1.f - alpha;
    float cb = alpha / (1.f + pii);
    float outs = g_c.outs[h];

    float ax=0.f, ay=0.f, az=0.f, aw=0.f;
    for (int c = 0; c < nc; ++c) {
        float4 p = *(const float4*)(g_pacc + (size_t)(b0 + c*64)*64 + c0);
        ax += p.x; ay += p.y; az += p.z; aw += p.w;
    }
    float4 v = *(const float4*)(g_v + (size_t)(h*T_N + i0 + row)*D_N + c0);
    float4 o;
    float p0 = ax*linv, p1 = ay*linv, p2 = az*linv, p3 = aw*linv;
    o.x = outs * (ca*p0 + cb*(p0 + pii*v.x));
    o.y = outs * (ca*p1 + cb*(p1 + pii*v.y));
    o.z = outs * (ca*p2 + cb*(p2 + pii*v.z));
    o.w = outs * (ca*p3 + cb*(p3 + pii*v.w));
    *(float4*)(g_y + (size_t)(i0 + row)*C_N + h*D_N + c0) = o;
}

// ---------------- launch ----------------
extern "C" void kernel_launch(void* const* d_in, const int* in_sizes, int n_in,
                              void* d_out, int out_size) {
    const float* x         = (const float*)d_in[0];
    const float* W_qkvg    = (const float*)d_in[1];
    const float* W_out     = (const float*)d_in[2];
    const float* lam       = (const float*)d_in[3];
    const float* log_tau   = (const float*)d_in[4];
    const float* logit_w   = (const float*)d_in[5];
    const float* beta      = (const float*)d_in[6];
    const float* out_scale = (const float*)d_in[7];
    const float* dp_scale  = (const float*)d_in[8];
    const float* logk_sc   = (const float*)d_in[9];
    const float* dt_logit  = (const float*)d_in[10];
    const float* gnw       = (const float*)d_in[11];
    float* out = (float*)d_out;

    float *y_p = nullptr, *op_p = nullptr;
    cudaGetSymbolAddress((void**)&y_p, g_y);
    cudaGetSymbolAddress((void**)&op_p, g_op);

    const int G64_SMEM = 2*STG64*4;
    cudaFuncSetAttribute(gemm_tf32_64, cudaFuncAttributeMaxDynamicSharedMemorySize, G64_SMEM);
    cudaFuncSetAttribute(attn_part, cudaFuncAttributeMaxDynamicSharedMemorySize, ATT_SMEM_BYTES);

    const_kernel<<<1, 32>>>(lam, log_tau, logit_w, beta, out_scale, dp_scale, logk_sc, dt_logit);
    gemm_tf32_64<<<dim3(3072/128, 1024/64), 256, G64_SMEM>>>(x, W_qkvg, nullptr, T_N, 4*C_N, C_N, C_N, 1, gnw, nullptr);
    attn_part<<<480, 256, ATT_SMEM_BYTES>>>();
    attn_combine<<<576, 256>>>();
    gemm_tf32_64<<<dim3(768/128, 1024/64, 3), 256, G64_SMEM>>>(y_p, W_out, op_p, T_N, C_N, C_N, 256, 0, nullptr, out);
}

// round 17
// speedup vs baseline: 1.0447x; 1.0447x over previous
#include <cuda_runtime.h>
#include <cuda_bf16.h>

#define T_N 1024
#define C_N 768
#define H_N 12
#define D_N 64
#define NT_N 8
#define LOG2E 1.4426950408889634f

// ---------------- scratch (static device globals; no allocation) ----------------
__device__ float g_q[H_N * T_N * D_N];       // [H][T][D]
__device__ float g_k[H_N * T_N * D_N];
__device__ float g_v[H_N * T_N * D_N];
__device__ float g_g[H_N * T_N * D_N];       // rmsnormed+tf32-quantized g (written by gemm epilogue)
__device__ float g_g2[H_N * T_N];            // ||ghat||^2 per (h,t)
__device__ float g_y[T_N * C_N];             // attention out, [T][C] layout
__device__ unsigned g_red[H_N][3];           // per-head max ||q||^2,||k||^2,g2 (uint-ordered; atomicMax idempotent across replays)
__device__ float g_op[3 * T_N * C_N];        // split-k partials for out projection

// split-j partials: 40 units per head (chunks of <=4 j-tiles), all at scale 2^-M
__device__ float g_pacc[H_N * 40 * 64 * 64]; // [h][unit][row][col]
__device__ float g_pl[H_N * 40 * 64];
__device__ float g_dw[H_N * 16 * 64];        // diag weights per (h,it,row)

// unit tables: heavy (4-tile) units first for scheduling
__constant__ int c_uit[40] = {15,15,15,15,14,14,14,13,13,13,12,12,12,11,11,11,10,10,9,9,8,8,7,7,6,5,4,3,
                              14,10,6,2, 13,9,5,1, 12,8,4,0};
__constant__ int c_uc[40]  = { 0, 1, 2, 3, 0, 1, 2, 0, 1, 2, 0, 1, 2, 0, 1, 2, 0, 1,0,1,0,1,0,1,0,0,0,0,
                               3, 2,1,0,  3,2,1,0,  3,2,1,0};
__constant__ int c_off[16] = {0,1,2,3,4,6,8,10,12,15,18,21,24,28,32,36};

struct Consts {
    float inv4tau[H_N][NT_N];
    float wte[H_N][NT_N];
    float neghb[H_N];
    float dpl[H_N];           // lam * dp_scale/(8*0.8)
    float glk[H_N];           // (1-lam) * logk_scale * ln2
    float outs[H_N];
    float fA[H_N], fB[H_N], i4t0[H_N];
    int   fastf[H_N];
    float alpha;
};
__device__ Consts g_c;

__device__ __forceinline__ float ex2f_(float x){ float y; asm("ex2.approx.ftz.f32 %0, %1;":"=f"(y):"f"(x)); return y; }
__device__ __forceinline__ float lg2f_(float x){ float y; asm("lg2.approx.ftz.f32 %0, %1;":"=f"(y):"f"(x)); return y; }
__device__ __forceinline__ unsigned f2tf32(float x){ unsigned y; asm("cvt.rna.tf32.f32 %0, %1;":"=r"(y):"f"(x)); return y; }

__device__ __forceinline__ void mma_tf32(float* d, const unsigned* a, const unsigned* b) {
    asm volatile(
      "mma.sync.aligned.m16n8k8.row.col.f32.tf32.tf32.f32 "
      "{%0,%1,%2,%3}, {%4,%5,%6,%7}, {%8,%9}, {%0,%1,%2,%3};\n"
      : "+f"(d[0]), "+f"(d[1]), "+f"(d[2]), "+f"(d[3])
      : "r"(a[0]), "r"(a[1]), "r"(a[2]), "r"(a[3]), "r"(b[0]), "r"(b[1]));
}

// ---------------- tf32 GEMM 64x128, double-buffered, k-range ----------------
// scatter=1: qkvg path with fused head-scatter + rmsnorm(g) + norm maxes
//            + (CTA (0,0) only) per-head Consts table computation
#define GS 36
#define STG64 ((64+128)*GS)

__global__ __launch_bounds__(256, 3) void gemm_tf32_64(const float* __restrict__ A,
        const float* __restrict__ B, float* __restrict__ C, int M, int N, int Kst,
        int klen, int scatter, const float* __restrict__ gnw,
        const float* lam_p, const float* log_tau, const float* logit_w,
        const float* beta, const float* out_scale, const float* dp_scale,
        const float* logk_scale, const float* dt_logit) {
    extern __shared__ unsigned gsm[];
    int tid = threadIdx.x;
    int lane = tid & 31, w = tid >> 5;
    int wm = w >> 2, wn = w & 3;
    int m0 = blockIdx.y*64, n0 = blockIdx.x*128;
    int k0 = blockIdx.z*klen;
    int lr = tid >> 3, lc = (tid & 7)*4;
    const float* Ap = A + (size_t)(m0+lr)*Kst + k0 + lc;
    const float* Bp = B + (size_t)(n0+lr)*Kst + k0 + lc;

    float acc[2][4][4];
    #pragma unroll
    for (int i = 0; i < 2; ++i)
        #pragma unroll
        for (int j = 0; j < 4; ++j)
            #pragma unroll
            for (int v = 0; v < 4; ++v) acc[i][j][v] = 0.f;

    int qa = lane >> 2, ra = lane & 3;

    float4 pra[2], prb[4];
    #pragma unroll
    for (int p = 0; p < 2; ++p) pra[p] = *(const float4*)(Ap + (size_t)p*32*Kst);
    #pragma unroll
    for (int p = 0; p < 4; ++p) prb[p] = *(const float4*)(Bp + (size_t)p*32*Kst);
    {
        unsigned* As = gsm;
        unsigned* Bs = gsm + 64*GS;
        #pragma unroll
        for (int p = 0; p < 2; ++p) {
            unsigned* as = As + (lr + p*32)*GS + lc;
            as[0]=f2tf32(pra[p].x); as[1]=f2tf32(pra[p].y); as[2]=f2tf32(pra[p].z); as[3]=f2tf32(pra[p].w);
        }
        #pragma unroll
        for (int p = 0; p < 4; ++p) {
            unsigned* bs = Bs + (lr + p*32)*GS + lc;
            bs[0]=f2tf32(prb[p].x); bs[1]=f2tf32(prb[p].y); bs[2]=f2tf32(prb[p].z); bs[3]=f2tf32(prb[p].w);
        }
    }
    __syncthreads();
    int cur = 0;

    for (int kb = 0; kb < klen; kb += 32) {
        bool nxt = (kb + 32 < klen);
        if (nxt) {
            #pragma unroll
            for (int p = 0; p < 2; ++p) pra[p] = *(const float4*)(Ap + (size_t)p*32*Kst + kb + 32);
            #pragma unroll
            for (int p = 0; p < 4; ++p) prb[p] = *(const float4*)(Bp + (size_t)p*32*Kst + kb + 32);
        }
        unsigned* As = gsm + cur*STG64;
        unsigned* Bs = As + 64*GS;
        #pragma unroll
        for (int ks = 0; ks < 4; ++ks) {
            unsigned af[2][4], bf[4][2];
            #pragma unroll
            for (int mt = 0; mt < 2; ++mt) {
                const unsigned* p = As + (wm*32 + mt*16 + qa)*GS + ks*8 + ra;
                af[mt][0] = p[0];
                af[mt][1] = p[8*GS];
                af[mt][2] = p[4];
                af[mt][3] = p[8*GS + 4];
            }
            #pragma unroll
            for (int nt = 0; nt < 4; ++nt) {
                const unsigned* p = Bs + (wn*32 + nt*8 + qa)*GS + ks*8 + ra;
                bf[nt][0] = p[0];
                bf[nt][1] = p[4];
            }
            #pragma unroll
            for (int mt = 0; mt < 2; ++mt)
                #pragma unroll
                for (int nt = 0; nt < 4; ++nt)
                    mma_tf32(acc[mt][nt], af[mt], bf[nt]);
        }
        if (nxt) {
            unsigned* As2 = gsm + (cur^1)*STG64;
            unsigned* Bs2 = As2 + 64*GS;
            #pragma unroll
            for (int p = 0; p < 2; ++p) {
                unsigned* as = As2 + (lr + p*32)*GS + lc;
                as[0]=f2tf32(pra[p].x); as[1]=f2tf32(pra[p].y); as[2]=f2tf32(pra[p].z); as[3]=f2tf32(pra[p].w);
            }
            #pragma unroll
            for (int p = 0; p < 4; ++p) {
                unsigned* bs = Bs2 + (lr + p*32)*GS + lc;
                bs[0]=f2tf32(prb[p].x); bs[1]=f2tf32(prb[p].y); bs[2]=f2tf32(prb[p].z); bs[3]=f2tf32(prb[p].w);
            }
            __syncthreads();
            cur ^= 1;
        }
    }

    if (!scatter) {
        float* Cp = C + (size_t)blockIdx.z*M*N;
        #pragma unroll
        for (int mt = 0; mt < 2; ++mt) {
            int row = m0 + wm*32 + mt*16 + qa;
            #pragma unroll
            for (int nt = 0; nt < 4; ++nt) {
                int col = n0 + wn*32 + nt*8 + ra*2;
                float2 c0 = {acc[mt][nt][0], acc[mt][nt][1]};
                float2 c1 = {acc[mt][nt][2], acc[mt][nt][3]};
                *(float2*)(Cp + (size_t)row*N + col) = c0;
                *(float2*)(Cp + (size_t)(row+8)*N + col) = c1;
            }
        }
        return;
    }

    // ---- scatter path: stage tile, fused rmsnorm(g)/norm maxes ----
    __syncthreads();   // stage buffers free
    float* epi = (float*)gsm;       // [64][132]
    #pragma unroll
    for (int mt = 0; mt < 2; ++mt) {
        int row = wm*32 + mt*16 + qa;
        #pragma unroll
        for (int nt = 0; nt < 4; ++nt) {
            int col = wn*32 + nt*8 + ra*2;
            float2 c0 = {acc[mt][nt][0], acc[mt][nt][1]};
            float2 c1 = {acc[mt][nt][2], acc[mt][nt][3]};
            *(float2*)(epi + row*132 + col) = c0;
            *(float2*)(epi + (row+8)*132 + col) = c1;
        }
    }
    __syncthreads();
    int sec = n0 / C_N;            // 0:q 1:k 2:v 3:g (uniform per CTA)
    int hh0 = (n0 % C_N) >> 6;     // first of two heads in this tile
    float* psm = epi + 64*132;     // 128 ss cells (tail of smem)

    if (sec != 2) {
        int pr = tid >> 1, hf = tid & 1;
        int row = pr >> 1, hd = pr & 1;
        const float* rp = epi + row*132 + hd*64 + hf*32;
        float ss = 0.f;
        #pragma unroll
        for (int c = 0; c < 32; c += 4) {
            float4 v = *(const float4*)(rp + c);
            ss += v.x*v.x + v.y*v.y + v.z*v.z + v.w*v.w;
        }
        ss += __shfl_xor_sync(0xffffffffu, ss, 1);
        if (sec == 3) {
            float r = rsqrtf(ss*(1.0f/D_N) + 1e-6f);
            float s2h = 0.f;
            int grow = (hh0 + hd)*T_N + m0 + row;
            #pragma unroll
            for (int c = 0; c < 32; c += 4) {
                int dd = hf*32 + c;
                float4 v = *(const float4*)(rp + c);
                float4 wv = *(const float4*)(gnw + dd);
                float4 qv;
                qv.x = __uint_as_float(f2tf32(v.x*r*wv.x));
                qv.y = __uint_as_float(f2tf32(v.y*r*wv.y));
                qv.z = __uint_as_float(f2tf32(v.z*r*wv.z));
                qv.w = __uint_as_float(f2tf32(v.w*r*wv.w));
                s2h += qv.x*qv.x + qv.y*qv.y + qv.z*qv.z + qv.w*qv.w;
                *(float4*)(g_g + (size_t)grow*D_N + dd) = qv;
            }
            s2h += __shfl_xor_sync(0xffffffffu, s2h, 1);
            if (hf == 0) { g_g2[grow] = s2h; psm[pr] = s2h; }
        } else {
            if (hf == 0) psm[pr] = ss;
        }
    }
    if (sec != 3) {
        float* base = (sec == 0) ? g_q : (sec == 1) ? g_k : g_v;
        #pragma unroll
        for (int p = 0; p < 8; ++p) {
            int f = tid + p*256;
            int row = f >> 5, c4 = (f & 31)*4;
            float4 v = *(const float4*)(epi + row*132 + c4);
            int hd = c4 >> 6, dd = c4 & 63;
            *(float4*)(base + ((size_t)((hh0+hd)*T_N + m0 + row))*D_N + dd) = v;
        }
    }
    __syncthreads();
    if (tid < 2 && sec != 2) {
        float mx = 0.f;
        #pragma unroll 4
        for (int rr = 0; rr < 64; ++rr) mx = fmaxf(mx, psm[rr*2 + tid]);
        int cell = (sec == 3) ? 2 : sec;
        atomicMax(&g_red[hh0 + tid][cell], __float_as_uint(mx));
    }

    // ---- Consts table (one CTA, off critical path; g_c read only by later launches) ----
    if (blockIdx.x == 0 && blockIdx.y == 0 && tid < H_N) {
        int h = tid;
        float lam = lam_p[0];
        float mx = -1e30f;
        for (int t = 0; t < NT_N; ++t) mx = fmaxf(mx, logit_w[h*NT_N+t]);
        float s = 0.f, e[NT_N];
        for (int t = 0; t < NT_N; ++t) { e[t] = expf(logit_w[h*NT_N+t]-mx); s += e[t]; }
        float W = 0.f;
        for (int t = 0; t < NT_N; ++t) { g_c.wte[h][t] = e[t]/s + 1e-12f; W += g_c.wte[h][t]; }
        for (int t = 0; t < NT_N; ++t) {
            float tau = fmaxf(expf(log_tau[h*NT_N+t]), 1e-6f);
            g_c.inv4tau[h][t] = 1.f/(4.f*tau);
        }
        float bc = fminf(fmaxf(beta[h], 0.5f), 2.5f);
        float neghb = -0.5f*bc;
        float dpc = dp_scale[h]/(8.0f*0.8f);
        float lks = logk_scale[h]*0.6931471805599453f;
        g_c.neghb[h] = neghb;
        g_c.dpl[h]   = lam*dpc;
        g_c.glk[h]   = (1.f-lam)*lks;
        g_c.outs[h]  = out_scale[h];
        int same = 1;
        for (int t = 1; t < NT_N; ++t) if (g_c.inv4tau[h][t] != g_c.inv4tau[h][0]) same = 0;
        g_c.fastf[h] = same;
        g_c.i4t0[h]  = g_c.inv4tau[h][0];
        g_c.fA[h]    = g_c.glk[h]*neghb;
        g_c.fB[h]    = g_c.glk[h]*log2f(W);
        if (h == 0) g_c.alpha = 0.1f/(1.f+expf(-dt_logit[0]));
    }
}

// ---------------- split-k add: out = p0 + p1 + p2 ----------------
__global__ __launch_bounds__(256) void addk_kernel(float* __restrict__ out) {
    int i = blockIdx.x*256 + threadIdx.x;     // float4 index, grid exact
    const float4* p0 = (const float4*)g_op;
    const float4* p1 = (const float4*)(g_op + T_N*C_N);
    const float4* p2 = (const float4*)(g_op + 2*T_N*C_N);
    float4 a = p0[i], b = p1[i], c = p2[i];
    float4 o;
    o.x = a.x + b.x + c.x;
    o.y = a.y + b.y + c.y;
    o.z = a.z + b.z + c.z;
    o.w = a.w + b.w + c.w;
    ((float4*)out)[i] = o;
}

// ---------------- split-j flash attention partial (fixed-max, paired LDS.64 frags) ----------------
#define QG_O   0                // uint2[64][68]: (q tf32, g tf32)
#define KG_O   8704             // uint2[64][68]: (k tf32, g tf32)
#define VS_O   17408            // 72 rows x 68 (row 64 = ones for row-sum, 65-71 zero)
#define PS_O   22304
#define G2I_O  26656
#define G2J_O  26720
#define DWS_O  26784
#define ATT_SMEM_WORDS 26848
#define ATT_SMEM_BYTES (ATT_SMEM_WORDS*4)

__global__ __launch_bounds__(256, 2) void attn_part() {
    extern __shared__ unsigned smu[];
    float* smf = (float*)smu;
    unsigned* Vs  = smu + VS_O;
    unsigned* Ps  = smu + PS_O;
    float* g2i_s = smf + G2I_O;
    float* g2j_s = smf + G2J_O;
    float* dws   = smf + DWS_O;

    int bid = blockIdx.x;
    int h = bid % H_N;
    int u = bid / H_N;
    int it = c_uit[u], cch = c_uc[u];
    int i0 = it * 64;
    int jt0 = cch*4, jt1 = min(jt0+3, it);
    int uidx = c_off[it] + cch;
    int tid = threadIdx.x;
    int lane = tid & 31, w = tid >> 5;
    int wm = w >> 1, wn = w & 1;
    int qa = lane >> 2, ra = lane & 3;
    int row0 = wm*16 + qa;

    int fast = g_c.fastf[h];
    float i4t0 = g_c.i4t0[h];
    float neghb = g_c.neghb[h];

    // ---- derive safe max M from reduced norms ----
    float M2;
    {
        float mq = __uint_as_float(g_red[h][0]);
        float mk = __uint_as_float(g_red[h][1]);
        float mg = __uint_as_float(g_red[h][2]);
        float dplL_ = g_c.dpl[h]*LOG2E;
        float bqk = fabsf(dplL_)*sqrtf(mq*mk);
        float smax = 4.f*mg + 1.f;
        float kmax;
        if (fast) {
            float a = g_c.fA[h]*LOG2E, b = g_c.fB[h]*LOG2E;
            float t1 = fmaf(a, log2f(fmaf(smax, i4t0, 1.f)), b);
            kmax = fmaxf(t1, b);
        } else {
            float glkL_ = g_c.glk[h]*LOG2E;
            float W = 0.f, Kmin = 0.f;
            #pragma unroll
            for (int t = 0; t < NT_N; ++t) {
                W += g_c.wte[h][t];
                Kmin += g_c.wte[h][t]*powf(fmaf(smax, g_c.inv4tau[h][t], 1.f), neghb);
            }
            kmax = fmaxf(glkL_*log2f(W), glkL_*log2f(Kmin));
        }
        M2 = bqk + kmax + 1.f;
    }
    float dplL = g_c.dpl[h]*LOG2E;
    float fAL  = g_c.fA[h]*LOG2E;
    float fBM  = g_c.fB[h]*LOG2E - M2;
    float glkL = g_c.glk[h]*LOG2E;
    float mneg = -M2;

    const float* qg  = g_q + (size_t)(h*T_N + i0)*D_N;
    const float* gig = g_g + (size_t)(h*T_N + i0)*D_N;
    #pragma unroll
    for (int p = 0; p < 4; ++p) {
        int e = tid + p*256;
        int r = e >> 4, dc = (e & 15)*4;
        float4 a = *(const float4*)(qg + r*D_N + dc);
        float4 b = *(const float4*)(gig + r*D_N + dc);   // already tf32-quantized
        uint4 w0, w1;
        w0.x = f2tf32(a.x); w0.y = __float_as_uint(b.x);
        w0.z = f2tf32(a.y); w0.w = __float_as_uint(b.y);
        w1.x = f2tf32(a.z); w1.y = __float_as_uint(b.z);
        w1.z = f2tf32(a.w); w1.w = __float_as_uint(b.w);
        *(uint4*)(smu + QG_O + (r*68 + dc)*2) = w0;
        *(uint4*)(smu + QG_O + (r*68 + dc)*2 + 4) = w1;
    }
    if (tid < 64) g2i_s[tid] = g_g2[h*T_N + i0 + tid];
    // ones row (64) + zero rows (65-71) of Vs — written once, never overwritten
    for (int z = tid; z < 8*68; z += 256)
        Vs[64*68 + z] = (z < 64) ? f2tf32(1.f) : 0u;

    float apv[5][4];
    #pragma unroll
    for (int nt = 0; nt < 5; ++nt)
        #pragma unroll
        for (int c = 0; c < 4; ++c) apv[nt][c] = 0.f;

    for (int jt = jt0; jt <= jt1; ++jt) {
        int j0 = jt*64;
        __syncthreads();   // prev tile's Ps/Vs reads done
        const float* kg  = g_k + (size_t)(h*T_N + j0)*D_N;
        const float* gjg = g_g + (size_t)(h*T_N + j0)*D_N;
        const float* vg  = g_v + (size_t)(h*T_N + j0)*D_N;
        #pragma unroll
        for (int p = 0; p < 4; ++p) {
            int e = tid + p*256;
            int r = e >> 4, dc = (e & 15)*4;
            float4 a = *(const float4*)(kg + r*D_N + dc);
            float4 b = *(const float4*)(gjg + r*D_N + dc);
            uint4 w0, w1;
            w0.x = f2tf32(a.x); w0.y = __float_as_uint(b.x);
            w0.z = f2tf32(a.y); w0.w = __float_as_uint(b.y);
            w1.x = f2tf32(a.z); w1.y = __float_as_uint(b.z);
            w1.z = f2tf32(a.w); w1.w = __float_as_uint(b.w);
            *(uint4*)(smu + KG_O + (r*68 + dc)*2) = w0;
            *(uint4*)(smu + KG_O + (r*68 + dc)*2 + 4) = w1;
            int j = e & 63, dg = (e >> 6)*4;
            float4 v = *(const float4*)(vg + j*D_N + dg);
            Vs[(dg+0)*68 + j] = f2tf32(v.x);
            Vs[(dg+1)*68 + j] = f2tf32(v.y);
            Vs[(dg+2)*68 + j] = f2tf32(v.z);
            Vs[(dg+3)*68 + j] = f2tf32(v.w);
        }
        if (tid < 64) g2j_s[tid] = g_g2[h*T_N + j0 + tid];
        __syncthreads();

        // ---- QK + GG MMAs (paired LDS.64 fragment loads) ----
        float dqk[4][4], dgg[4][4];
        #pragma unroll
        for (int nt = 0; nt < 4; ++nt)
            #pragma unroll
            for (int c = 0; c < 4; ++c) { dqk[nt][c] = 0.f; dgg[nt][c] = 0.f; }

        #pragma unroll
        for (int ks = 0; ks < 8; ++ks) {
            int kc = ks*8 + ra;
            const uint2* qgp = (const uint2*)(smu + QG_O) + row0*68 + kc;
            uint2 w0 = qgp[0], w1 = qgp[8*68], w2 = qgp[4], w3 = qgp[8*68+4];
            unsigned af[4] = {w0.x, w1.x, w2.x, w3.x};
            unsigned gf[4] = {w0.y, w1.y, w2.y, w3.y};
            #pragma unroll
            for (int nt = 0; nt < 4; ++nt) {
                int nb = wn*32 + nt*8 + qa;
                const uint2* kgp = (const uint2*)(smu + KG_O) + nb*68 + kc;
                uint2 u0 = kgp[0], u1 = kgp[4];
                unsigned bf[2] = {u0.x, u1.x};
                unsigned bgf[2] = {u0.y, u1.y};
                mma_tf32(dqk[nt], af, bf);
                mma_tf32(dgg[nt], gf, bgf);
            }
        }

        // ---- epilogue: p = 2^(score - M) ----
        int diag = (jt == it);
        if (!diag && fast) {
            #pragma unroll
            for (int nt = 0; nt < 4; ++nt) {
                #pragma unroll
                for (int c = 0; c < 4; ++c) {
                    int rl = row0 + (c >> 1)*8;
                    int cl = wn*32 + nt*8 + 2*ra + (c & 1);
                    float s = fmaxf(g2i_s[rl] + g2j_s[cl] - 2.f*dgg[nt][c], 0.f);
                    dqk[nt][c] = ex2f_(fmaf(dqk[nt][c], dplL,
                                     fmaf(fAL, lg2f_(fmaf(s, i4t0, 1.f)), fBM)));
                }
            }
        } else {
            #pragma unroll
            for (int nt = 0; nt < 4; ++nt) {
                #pragma unroll
                for (int c = 0; c < 4; ++c) {
                    int rh = c >> 1, pp = c & 1;
                    int rl = row0 + rh*8;
                    int cl = wn*32 + nt*8 + 2*ra + pp;
                    float p = 0.f;
                    if (j0 + cl <= i0 + rl) {
                        float s = fmaxf(g2i_s[rl] + g2j_s[cl] - 2.f*dgg[nt][c], 0.f);
                        float blc;
                        if (fast) {
                            blc = fmaf(dqk[nt][c], dplL, fmaf(fAL, lg2f_(fmaf(s, i4t0, 1.f)), fBM));
                        } else {
                            float Ksum = 0.f;
                            #pragma unroll
                            for (int t = 0; t < 8; ++t) {
                                float uu = fmaf(s, g_c.inv4tau[h][t], 1.f);
                                Ksum = fmaf(g_c.wte[h][t], ex2f_(neghb * lg2f_(uu)), Ksum);
                            }
                            blc = fmaf(dqk[nt][c], dplL, fmaf(glkL, lg2f_(Ksum), mneg));
                        }
                        p = ex2f_(blc);
                    }
                    dqk[nt][c] = p;
                }
                if (diag) {
                    int cl = wn*32 + nt*8 + 2*ra;
                    if (row0 == cl) dws[row0] = dqk[nt][0];
                    else if (row0 == cl+1) dws[row0] = dqk[nt][1];
                    if (row0+8 == cl) dws[row0+8] = dqk[nt][2];
                    else if (row0+8 == cl+1) dws[row0+8] = dqk[nt][3];
                }
            }
        }
        // shared Ps stores (tf32)
        #pragma unroll
        for (int nt = 0; nt < 4; ++nt) {
            int cl = wn*32 + nt*8 + 2*ra;
            uint2 s0; s0.x = f2tf32(dqk[nt][0]); s0.y = f2tf32(dqk[nt][1]);
            uint2 s1; s1.x = f2tf32(dqk[nt][2]); s1.y = f2tf32(dqk[nt][3]);
            *(uint2*)(Ps + row0*68 + cl) = s0;
            *(uint2*)(Ps + (row0+8)*68 + cl) = s1;
        }
        __syncthreads();   // Ps (and dws) visible

        // ---- PV MMAs (k=64; wn==1 adds ones-column for row-sum l) ----
        #pragma unroll
        for (int ks = 0; ks < 8; ++ks) {
            int kc = ks*8 + ra;
            const unsigned* pp_ = Ps + row0*68 + kc;
            unsigned pf[4] = {pp_[0], pp_[8*68], pp_[4], pp_[8*68+4]};
            #pragma unroll
            for (int nt = 0; nt < 5; ++nt) {
                if (nt == 4 && wn == 0) break;
                const unsigned* vp = Vs + (wn*32 + nt*8 + qa)*68 + kc;
                unsigned vf[2] = {vp[0], vp[4]};
                mma_tf32(apv[nt], pf, vf);
            }
        }
    }

    if (it < 4) {
        // ---- single-chunk unit: finalize directly into g_y (skip partials) ----
        float* Ls = g2j_s;   // reuse: 64 row sums
        if (wn == 1 && ra == 0) { Ls[row0] = apv[4][0]; Ls[row0+8] = apv[4][2]; }
        __syncthreads();
        float alpha = g_c.alpha;
        float ca = 1.f - alpha;
        float outs = g_c.outs[h];
        #pragma unroll
        for (int rh = 0; rh < 2; ++rh) {
            int row = row0 + rh*8;
            float linv = 1.f / fmaxf(Ls[row], 1e-33f);
            float pii = dws[row] * linv;
            float cb = alpha / (1.f + pii);
            #pragma unroll
            for (int nt = 0; nt < 4; ++nt) {
                int cl = wn*32 + nt*8 + 2*ra;
                float p0 = apv[nt][2*rh]*linv, p1 = apv[nt][2*rh+1]*linv;
                float2 v = *(const float2*)(g_v + (size_t)(h*T_N + i0 + row)*D_N + cl);
                float2 o;
                o.x = outs * (ca*p0 + cb*(p0 + pii*v.x));
                o.y = outs * (ca*p1 + cb*(p1 + pii*v.y));
                *(float2*)(g_y + (size_t)(i0 + row)*C_N + h*D_N + cl) = o;
            }
        }
        return;
    }

    // ---- write partials (all at common scale 2^-M, no merge needed) ----
    int base = (h*40 + uidx)*64;
    #pragma unroll
    for (int nt = 0; nt < 4; ++nt) {
        int cl = wn*32 + nt*8 + 2*ra;
        float2 a0 = {apv[nt][0], apv[nt][1]};
        float2 a1 = {apv[nt][2], apv[nt][3]};
        *(float2*)(g_pacc + (size_t)(base + row0)*64 + cl) = a0;
        *(float2*)(g_pacc + (size_t)(base + row0 + 8)*64 + cl) = a1;
    }
    if (wn == 1 && ra == 0) {
        g_pl[base + row0]     = apv[4][0];
        g_pl[base + row0 + 8] = apv[4][2];
    }
    if (jt1 == it && tid < 64) g_dw[(h*16 + it)*64 + tid] = dws[tid];
}

// ---------------- combine partials -> g_y (it>=4 only; quarter-split grid) ----------------
__global__ __launch_bounds__(256) void attn_combine() {
    int bid = blockIdx.x;                 // 576 = 12 heads x 12 itiles(4..15) x 4 quarters
    int h = bid % H_N;
    int rest = bid / H_N;                 // 0..47
    int it = 4 + (rest >> 2), quarter = rest & 3;
    int i0 = it * 64;
    int nc = it/4 + 1;
    int tid = threadIdx.x;
    int row = tid >> 2;
    int c0 = (tid & 3)*4 + quarter*16;
    int b0 = (h*40 + c_off[it])*64 + row;

    float L = 0.f;
    for (int c = 0; c < nc; ++c) L += g_pl[b0 + c*64];
    float linv = 1.f / fmaxf(L, 1e-33f);
    float pii = g_dw[(h*16 + it)*64 + row] * linv;
    float alpha = g_c.alpha;
    float ca = 1.f - alpha;
    float cb = alpha / (1.f + pii);
    float outs = g_c.outs[h];

    float ax=0.f, ay=0.f, az=0.f, aw=0.f;
    for (int c = 0; c < nc; ++c) {
        float4 p = *(const float4*)(g_pacc + (size_t)(b0 + c*64)*64 + c0);
        ax += p.x; ay += p.y; az += p.z; aw += p.w;
    }
    float4 v = *(const float4*)(g_v + (size_t)(h*T_N + i0 + row)*D_N + c0);
    float4 o;
    float p0 = ax*linv, p1 = ay*linv, p2 = az*linv, p3 = aw*linv;
    o.x = outs * (ca*p0 + cb*(p0 + pii*v.x));
    o.y = outs * (ca*p1 + cb*(p1 + pii*v.y));
    o.z = outs * (ca*p2 + cb*(p2 + pii*v.z));
    o.w = outs * (ca*p3 + cb*(p3 + pii*v.w));
    *(float4*)(g_y + (size_t)(i0 + row)*C_N + h*D_N + c0) = o;
}

// ---------------- launch ----------------
extern "C" void kernel_launch(void* const* d_in, const int* in_sizes, int n_in,
                              void* d_out, int out_size) {
    const float* x         = (const float*)d_in[0];
    const float* W_qkvg    = (const float*)d_in[1];
    const float* W_out     = (const float*)d_in[2];
    const float* lam       = (const float*)d_in[3];
    const float* log_tau   = (const float*)d_in[4];
    const float* logit_w   = (const float*)d_in[5];
    const float* beta      = (const float*)d_in[6];
    const float* out_scale = (const float*)d_in[7];
    const float* dp_scale  = (const float*)d_in[8];
    const float* logk_sc   = (const float*)d_in[9];
    const float* dt_logit  = (const float*)d_in[10];
    const float* gnw       = (const float*)d_in[11];
    float* out = (float*)d_out;

    float *y_p = nullptr, *op_p = nullptr;
    cudaGetSymbolAddress((void**)&y_p, g_y);
    cudaGetSymbolAddress((void**)&op_p, g_op);

    const int G64_SMEM = 2*STG64*4;
    cudaFuncSetAttribute(gemm_tf32_64, cudaFuncAttributeMaxDynamicSharedMemorySize, G64_SMEM);
    cudaFuncSetAttribute(attn_part, cudaFuncAttributeMaxDynamicSharedMemorySize, ATT_SMEM_BYTES);

    gemm_tf32_64<<<dim3(3072/128, 1024/64), 256, G64_SMEM>>>(x, W_qkvg, nullptr, T_N, 4*C_N, C_N, C_N, 1, gnw,
        lam, log_tau, logit_w, beta, out_scale, dp_scale, logk_sc, dt_logit);
    attn_part<<<480, 256, ATT_SMEM_BYTES>>>();
    attn_combine<<<576, 256>>>();
    gemm_tf32_64<<<dim3(768/128, 1024/64, 3), 256, G64_SMEM>>>(y_p, W_out, op_p, T_N, C_N, C_N, 256, 0, nullptr,
        nullptr, nullptr, nullptr, nullptr, nullptr, nullptr, nullptr, nullptr);
    addk_kernel<<<(T_N*C_N/4)/256, 256>>>(out);
}